// round 11
// baseline (speedup 1.0000x reference)
#include <cuda_runtime.h>
#include <cstdint>

typedef unsigned long long ull;

// ---------- packed f32x2 helpers (sm_10x; ptxas never emits FFMA2 from C++) ----------
__device__ __forceinline__ ull pk(float lo, float hi) {
    ull r; asm("mov.b64 %0,{%1,%2};" : "=l"(r) : "f"(lo), "f"(hi)); return r;
}
__device__ __forceinline__ void upk(ull v, float& lo, float& hi) {
    asm("mov.b64 {%0,%1},%2;" : "=f"(lo), "=f"(hi) : "l"(v));
}
__device__ __forceinline__ ull fma2(ull a, ull b, ull c) {
    ull d; asm("fma.rn.f32x2 %0,%1,%2,%3;" : "=l"(d) : "l"(a), "l"(b), "l"(c)); return d;
}
__device__ __forceinline__ ull mul2(ull a, ull b) {
    ull d; asm("mul.rn.f32x2 %0,%1,%2;" : "=l"(d) : "l"(a), "l"(b)); return d;
}

// Per-step constants of the combined RZ(c)∘RY(b) Bloch rotation, stored as
// duplicated float2 so a single LDS.64 yields a ready packed f32x2 operand.
// Layout per step t (8 entries): [A=cc*cb, Bc=cc*sb, -sc, D=sc*cb, E=sc*sb, cc, -sb, cb]
__device__ float2 g_const[32 * 8];

__global__ void prep_kernel(const float* __restrict__ theta) {
    int t = threadIdx.x;
    if (t < 32) {
        float bang = theta[2 * t + 0];
        float cang = theta[2 * t + 1];
        float sb, cb, sc, cc;
        sincosf(bang, &sb, &cb);   // FULL angles (Bloch-vector rotations)
        sincosf(cang, &sc, &cc);
        float2* p = &g_const[t * 8];
        p[0] = make_float2(cc * cb, cc * cb);
        p[1] = make_float2(cc * sb, cc * sb);
        p[2] = make_float2(-sc, -sc);
        p[3] = make_float2(sc * cb, sc * cb);
        p[4] = make_float2(sc * sb, sc * sb);
        p[5] = make_float2(cc, cc);
        p[6] = make_float2(-sb, -sb);
        p[7] = make_float2(cb, cb);
    }
}

#define TPB 128           // threads per block
#define RPB 256           // rows (batch elements) per block: 2 per thread
#define PAD 33            // smem row stride in floats -> conflict-free column reads

__global__ __launch_bounds__(TPB)
void qubit_bloch_kernel(const float* __restrict__ x,
                        const float* __restrict__ w,
                        const float* __restrict__ bias,
                        float* __restrict__ out,
                        int B) {
    __shared__ float  s_x[RPB * PAD];   // 33792 B
    __shared__ float2 s_c[32 * 8];      //  2048 B

    const int  tid  = threadIdx.x;
    const long base = (long)blockIdx.x * RPB;

    // ---- coalesced gmem -> smem staging (bank-conflict-free writes: bank=(33*row+col)%32) ----
    const float* gx = x + base * 32;
    const int limit = (int)(((long)B - base) * 32 < (long)RPB * 32 ? ((long)B - base) * 32
                                                                   : (long)RPB * 32);
    #pragma unroll 4
    for (int k = tid; k < RPB * 32; k += TPB) {
        float v = (k < limit) ? gx[k] : 0.0f;
        s_x[(k >> 5) * PAD + (k & 31)] = v;
    }
    for (int k = tid; k < 32 * 8; k += TPB) s_c[k] = g_const[k];
    __syncthreads();

    // ---- simulate 2 batch elements per thread with packed f32x2 state ----
    // Bloch state starts at (0,0,1); per step:
    //   RX(x):  Y1 = cx*Y - sx*Z ;  Z1 = sx*Y + cx*Z
    //   C=RZ∘RY: X' = A*X - sc*Y1 + Bc*Z1
    //            Y' = D*X + cc*Y1 + E*Z1
    //            Z' = -sb*X + cb*Z1
    ull X = pk(0.0f, 0.0f);
    ull Y = X;
    ull Z = pk(1.0f, 1.0f);

    const float* r0 = &s_x[tid * PAD];
    const float* r1 = &s_x[(tid + TPB) * PAD];

    #pragma unroll
    for (int t = 0; t < 32; t++) {
        float xa = r0[t];
        float xb = r1[t];
        float sxa, cxa, sxb, cxb;
        __sincosf(xa, &sxa, &cxa);
        __sincosf(xb, &sxb, &cxb);
        ull cx  = pk(cxa, cxb);
        ull sx  = pk(sxa, sxb);
        ull nsx = pk(-sxa, -sxb);

        const ull* C = (const ull*)&s_c[t * 8];   // broadcast LDS.64 reads

        ull Y1 = fma2(cx, Y, mul2(nsx, Z));
        ull Z1 = fma2(cx, Z, mul2(sx, Y));
        ull Xn = fma2(C[0], X, fma2(C[1], Z1, mul2(C[2], Y1)));
        ull Yn = fma2(C[3], X, fma2(C[4], Z1, mul2(C[5], Y1)));
        ull Zn = fma2(C[7], Z1, mul2(C[6], X));
        X = Xn; Y = Yn; Z = Zn;
    }

    float za, zb;
    upk(Z, za, zb);
    const float ww = *w;
    const float bb = *bias;

    const long i0 = base + tid;
    const long i1 = base + TPB + tid;
    if (i0 < B) out[i0] = za * ww + bb;   // coalesced stores
    if (i1 < B) out[i1] = zb * ww + bb;
}

extern "C" void kernel_launch(void* const* d_in, const int* in_sizes, int n_in,
                              void* d_out, int out_size) {
    const float* x     = (const float*)d_in[0];   // [B, 32] f32
    const float* theta = (const float*)d_in[1];   // [32, 2] f32
    const float* w     = (const float*)d_in[2];   // [1, 1]  f32
    const float* b     = (const float*)d_in[3];   // [1]     f32
    float* out = (float*)d_out;

    const int B = in_sizes[0] / 32;

    prep_kernel<<<1, 32>>>(theta);
    const int blocks = (B + RPB - 1) / RPB;
    qubit_bloch_kernel<<<blocks, TPB>>>(x, w, b, out, B);
}

// round 12
// speedup vs baseline: 1.6477x; 1.6477x over previous
#include <cuda_runtime.h>
#include <cstdint>

typedef unsigned long long ull;

// ---------- packed f32x2 helpers (sm_10x; ptxas never emits FFMA2 from C++) ----------
__device__ __forceinline__ ull pk(float lo, float hi) {
    ull r; asm("mov.b64 %0,{%1,%2};" : "=l"(r) : "f"(lo), "f"(hi)); return r;
}
__device__ __forceinline__ void upk(ull v, float& lo, float& hi) {
    asm("mov.b64 {%0,%1},%2;" : "=f"(lo), "=f"(hi) : "l"(v));
}
__device__ __forceinline__ ull fma2(ull a, ull b, ull c) {
    ull d; asm("fma.rn.f32x2 %0,%1,%2,%3;" : "=l"(d) : "l"(a), "l"(b), "l"(c)); return d;
}
__device__ __forceinline__ ull mul2(ull a, ull b) {
    ull d; asm("mul.rn.f32x2 %0,%1,%2;" : "=l"(d) : "l"(a), "l"(b)); return d;
}

#define TPB 128           // threads per block
#define RPB 256           // rows (batch elements) per block: 2 per thread
#define PAD 33            // smem row stride in floats -> conflict-free column reads

__global__ __launch_bounds__(TPB, 6)
void qubit_bloch_kernel(const float* __restrict__ x,
                        const float* __restrict__ theta,
                        const float* __restrict__ w,
                        const float* __restrict__ bias,
                        float* __restrict__ out,
                        int B) {
    __shared__ float  s_x[RPB * PAD];   // 33792 B
    __shared__ float2 s_c[32 * 8];      //  2048 B (duplicated f32x2 step constants)

    const int  tid  = threadIdx.x;
    const long base = (long)blockIdx.x * RPB;

    // ---- warp 0: compute per-step RZ(c)∘RY(b) Bloch-rotation constants in-block ----
    // (fused former prep kernel; theta is ~0.01 so precise sincosf hits the fast path)
    if (tid < 32) {
        float bang = theta[2 * tid + 0];
        float cang = theta[2 * tid + 1];
        float sb, cb, sc, cc;
        sincosf(bang, &sb, &cb);
        sincosf(cang, &sc, &cc);
        float2* p = &s_c[tid * 8];
        p[0] = make_float2(cc * cb, cc * cb);
        p[1] = make_float2(cc * sb, cc * sb);
        p[2] = make_float2(-sc, -sc);
        p[3] = make_float2(sc * cb, sc * cb);
        p[4] = make_float2(sc * sb, sc * sb);
        p[5] = make_float2(cc, cc);
        p[6] = make_float2(-sb, -sb);
        p[7] = make_float2(cb, cb);
    }

    // ---- coalesced float4 gmem -> smem staging (high MLP), pad-33 scalar STS ----
    // STS banks: (16*i + 33*(l>>3) + 4*(l&7)) mod 32 covers all 32 banks: conflict-free.
    if (base + RPB <= (long)B) {
        const float4* gx4 = (const float4*)(x + base * 32);
        #pragma unroll
        for (int i = 0; i < (RPB * 8) / TPB; i++) {       // 16 LDG.128 per thread
            int k4 = i * TPB + tid;
            float4 v = __ldcs(&gx4[k4]);                  // streaming: no L2 reuse
            int row = k4 >> 3;
            int col = (k4 & 7) * 4;
            float* p = &s_x[row * PAD + col];
            p[0] = v.x; p[1] = v.y; p[2] = v.z; p[3] = v.w;
        }
    } else {  // tail block (generic, cold path)
        const float* gx = x + base * 32;
        const long rem = ((long)B - base) * 32;
        for (int k = tid; k < RPB * 32; k += TPB) {
            float v = (k < rem) ? gx[k] : 0.0f;
            s_x[(k >> 5) * PAD + (k & 31)] = v;
        }
    }
    __syncthreads();

    // ---- simulate 2 batch elements per thread with packed f32x2 Bloch state ----
    // start (0,0,1); per step:
    //   RX(x):  Y1 = cx*Y - sx*Z ;  Z1 = sx*Y + cx*Z
    //   RZ∘RY:  X' = A*X - sc*Y1 + Bc*Z1
    //           Y' = D*X + cc*Y1 + E*Z1
    //           Z' = -sb*X + cb*Z1
    ull X = pk(0.0f, 0.0f);
    ull Y = X;
    ull Z = pk(1.0f, 1.0f);

    const float* r0 = &s_x[tid * PAD];
    const float* r1 = &s_x[(tid + TPB) * PAD];

    #pragma unroll
    for (int t = 0; t < 32; t++) {
        float xa = r0[t];
        float xb = r1[t];
        float sxa, cxa, sxb, cxb;
        __sincosf(xa, &sxa, &cxa);
        __sincosf(xb, &sxb, &cxb);
        ull cx  = pk(cxa, cxb);
        ull sx  = pk(sxa, sxb);
        ull nsx = pk(-sxa, -sxb);

        const ull* C = (const ull*)&s_c[t * 8];   // broadcast LDS.64 reads

        ull Y1 = fma2(cx, Y, mul2(nsx, Z));
        ull Z1 = fma2(cx, Z, mul2(sx, Y));
        ull Xn = fma2(C[0], X, fma2(C[1], Z1, mul2(C[2], Y1)));
        ull Yn = fma2(C[3], X, fma2(C[4], Z1, mul2(C[5], Y1)));
        ull Zn = fma2(C[7], Z1, mul2(C[6], X));
        X = Xn; Y = Yn; Z = Zn;
    }

    float za, zb;
    upk(Z, za, zb);
    const float ww = __ldg(w);
    const float bb = __ldg(bias);

    const long i0 = base + tid;
    const long i1 = base + TPB + tid;
    if (i0 < B) __stcs(&out[i0], za * ww + bb);   // coalesced streaming stores
    if (i1 < B) __stcs(&out[i1], zb * ww + bb);
}

extern "C" void kernel_launch(void* const* d_in, const int* in_sizes, int n_in,
                              void* d_out, int out_size) {
    const float* x     = (const float*)d_in[0];   // [B, 32] f32
    const float* theta = (const float*)d_in[1];   // [32, 2] f32
    const float* w     = (const float*)d_in[2];   // [1, 1]  f32
    const float* b     = (const float*)d_in[3];   // [1]     f32
    float* out = (float*)d_out;

    const int B = in_sizes[0] / 32;
    const int blocks = (B + RPB - 1) / RPB;
    qubit_bloch_kernel<<<blocks, TPB>>>(x, theta, w, b, out, B);
}